// round 4
// baseline (speedup 1.0000x reference)
#include <cuda_runtime.h>
#include <cuda_bf16.h>

#define T_SEQ 4096
#define B_SZ  4
#define D_IN  1024
#define P_DIM 64
#define M_ROWS (B_SZ * T_SEQ)   // 16384

// qkv scratch: [head (q/k/v)][m = b*T + t][p]
__device__ __align__(16) float g_qkv[3u * M_ROWS * P_DIM];

// ---------------------------------------------------------------------------
// QKV projection: (16384 x 1024) @ (1024 x 192) + bias, scattered into q/k/v
// Block: 64(M) x 64(N) tile, 256 threads, 4x4 micro-tile, k-tile 32.
// blockIdx.y = head (0=q,1=k,2=v) since N tiles align with heads.
// ---------------------------------------------------------------------------
__global__ __launch_bounds__(256) void qkv_gemm_kernel(
    const float* __restrict__ x,
    const float* __restrict__ W,
    const float* __restrict__ bias)
{
    __shared__ float As[32][68];   // [k][m] (transposed for inner loop)
    __shared__ float Bs[32][68];   // [k][n]

    const int m0   = blockIdx.x * 64;
    const int head = blockIdx.y;
    const int n0   = head * 64;
    const int tid  = threadIdx.x;
    const int tx   = tid & 15;
    const int ty   = tid >> 4;

    float acc[4][4];
#pragma unroll
    for (int i = 0; i < 4; i++)
#pragma unroll
        for (int j = 0; j < 4; j++) acc[i][j] = 0.f;

    for (int k0 = 0; k0 < D_IN; k0 += 32) {
        // load A tile: 64 rows x 32 k  (512 float4 slots)
#pragma unroll
        for (int i = 0; i < 2; i++) {
            int s   = tid + i * 256;
            int row = s >> 3;
            int kc  = s & 7;
            float4 xv = *(const float4*)&x[(size_t)(m0 + row) * D_IN + k0 + kc * 4];
            As[kc * 4 + 0][row] = xv.x;
            As[kc * 4 + 1][row] = xv.y;
            As[kc * 4 + 2][row] = xv.z;
            As[kc * 4 + 3][row] = xv.w;
        }
        // load B tile: 32 k x 64 n (512 float4 slots)
#pragma unroll
        for (int i = 0; i < 2; i++) {
            int s  = tid + i * 256;
            int kk = s >> 4;
            int nc = s & 15;
            *(float4*)&Bs[kk][nc * 4] =
                *(const float4*)&W[(size_t)(k0 + kk) * 192 + n0 + nc * 4];
        }
        __syncthreads();

#pragma unroll
        for (int kk = 0; kk < 32; kk++) {
            float4 a4 = *(float4*)&As[kk][ty * 4];
            float4 b4 = *(float4*)&Bs[kk][tx * 4];
            float av[4] = {a4.x, a4.y, a4.z, a4.w};
            float bv[4] = {b4.x, b4.y, b4.z, b4.w};
#pragma unroll
            for (int i = 0; i < 4; i++)
#pragma unroll
                for (int j = 0; j < 4; j++)
                    acc[i][j] += av[i] * bv[j];
        }
        __syncthreads();
    }

    float4 bb = *(const float4*)&bias[n0 + tx * 4];
    float bv[4] = {bb.x, bb.y, bb.z, bb.w};
    float* outp = g_qkv + (size_t)head * M_ROWS * P_DIM;
#pragma unroll
    for (int i = 0; i < 4; i++) {
        int m = m0 + ty * 4 + i;
        float4 o;
        o.x = acc[i][0] + bv[0];
        o.y = acc[i][1] + bv[1];
        o.z = acc[i][2] + bv[2];
        o.w = acc[i][3] + bv[3];
        *(float4*)&outp[(size_t)m * P_DIM + tx * 4] = o;
    }
}

// ---------------------------------------------------------------------------
// Flash-style causal attention. Block = (query tile of 64, batch).
// 256 threads: r = tid>>2 (query row), g = tid&3.
//   - thread g owns keys  j = jj*4 + g   (jj 0..7)   -> conflict-free K reads
//   - thread g owns dim chunks c4 = c*4+g (c 0..3)   -> conflict-free V reads
// Key tile = 32. Online softmax with per-row group-of-4 shuffle reductions.
// ---------------------------------------------------------------------------
__global__ __launch_bounds__(256) void attn_kernel(float* __restrict__ out)
{
    __shared__ float Qs[64][68];
    __shared__ float Ks[32][68];
    __shared__ float Vs[32][68];
    __shared__ float Ps[64][36];

    const int qt  = blockIdx.x;     // 0..63
    const int b   = blockIdx.y;     // 0..3
    const int tid = threadIdx.x;
    const int r   = tid >> 2;
    const int g   = tid & 3;

    const float* qg = g_qkv;
    const float* kg = g_qkv + (size_t)M_ROWS * P_DIM;
    const float* vg = g_qkv + (size_t)2 * M_ROWS * P_DIM;

    const int qrow0 = b * T_SEQ + qt * 64;

    // load Q tile: 64 rows x 16 float4 = 1024 slots, 4 per thread
#pragma unroll
    for (int i = 0; i < 4; i++) {
        int s   = tid + i * 256;
        int row = s >> 4;
        int c   = s & 15;
        *(float4*)&Qs[row][c * 4] =
            *(const float4*)&qg[(size_t)(qrow0 + row) * P_DIM + c * 4];
    }

    float o[16];
#pragma unroll
    for (int d = 0; d < 16; d++) o[d] = 0.f;
    float m = -1e30f;
    float l = 0.f;

    const int tglob = qt * 64 + r;          // query index within batch
    const int nkt   = 2 * qt + 2;           // key tiles of 32 covering [0, qt*64+64)

    for (int kt = 0; kt < nkt; kt++) {
        __syncthreads();   // previous PV/Ps reads done before overwrite; also Qs ready
        const int krow0 = b * T_SEQ + kt * 32;
#pragma unroll
        for (int i = 0; i < 2; i++) {
            int s   = tid + i * 256;
            int row = s >> 4;
            int c   = s & 15;
            *(float4*)&Ks[row][c * 4] =
                *(const float4*)&kg[(size_t)(krow0 + row) * P_DIM + c * 4];
            *(float4*)&Vs[row][c * 4] =
                *(const float4*)&vg[(size_t)(krow0 + row) * P_DIM + c * 4];
        }
        __syncthreads();

        // S = q . k for this thread's 8 keys (interleaved j = jj*4+g)
        float sv[8];
#pragma unroll
        for (int jj = 0; jj < 8; jj++) sv[jj] = 0.f;
#pragma unroll
        for (int p4 = 0; p4 < 16; p4++) {
            float4 q4 = *(float4*)&Qs[r][p4 * 4];
#pragma unroll
            for (int jj = 0; jj < 8; jj++) {
                float4 k4 = *(float4*)&Ks[jj * 4 + g][p4 * 4];
                sv[jj] += q4.x * k4.x + q4.y * k4.y + q4.z * k4.z + q4.w * k4.w;
            }
        }

        // causal mask + tile max
        const int kbase = kt * 32;
        float tmax = -1e30f;
#pragma unroll
        for (int jj = 0; jj < 8; jj++) {
            int jg = kbase + jj * 4 + g;
            if (jg > tglob) sv[jj] = -1e30f;
            tmax = fmaxf(tmax, sv[jj]);
        }
        tmax = fmaxf(tmax, __shfl_xor_sync(0xffffffffu, tmax, 1));
        tmax = fmaxf(tmax, __shfl_xor_sync(0xffffffffu, tmax, 2));

        float mnew  = fmaxf(m, tmax);
        float scale = __expf(m - mnew);
        float lsum  = 0.f;
#pragma unroll
        for (int jj = 0; jj < 8; jj++) {
            float p = __expf(sv[jj] - mnew);
            lsum += p;
            Ps[r][jj * 4 + g] = p;
        }
        lsum += __shfl_xor_sync(0xffffffffu, lsum, 1);
        lsum += __shfl_xor_sync(0xffffffffu, lsum, 2);
        l = l * scale + lsum;
        m = mnew;
#pragma unroll
        for (int d = 0; d < 16; d++) o[d] *= scale;

        __syncthreads();

        // O += P @ V  (thread owns dim chunks (c*4+g)*4 .. +3)
#pragma unroll
        for (int j = 0; j < 32; j++) {
            float pv = Ps[r][j];
#pragma unroll
            for (int c = 0; c < 4; c++) {
                float4 v4 = *(float4*)&Vs[j][(c * 4 + g) * 4];
                o[c * 4 + 0] += pv * v4.x;
                o[c * 4 + 1] += pv * v4.y;
                o[c * 4 + 2] += pv * v4.z;
                o[c * 4 + 3] += pv * v4.w;
            }
        }
    }

    float inv = 1.0f / l;
    float* orow = out + (size_t)(b * T_SEQ + tglob) * P_DIM;
#pragma unroll
    for (int c = 0; c < 4; c++) {
        float4 ov;
        ov.x = o[c * 4 + 0] * inv;
        ov.y = o[c * 4 + 1] * inv;
        ov.z = o[c * 4 + 2] * inv;
        ov.w = o[c * 4 + 3] * inv;
        *(float4*)&orow[(c * 4 + g) * 4] = ov;
    }
}

extern "C" void kernel_launch(void* const* d_in, const int* in_sizes, int n_in,
                              void* d_out, int out_size)
{
    const float* x    = (const float*)d_in[0];   // (4, 4096, 1024)
    const float* W    = (const float*)d_in[1];   // (1024, 192)
    const float* bias = (const float*)d_in[2];   // (192,)
    float* out        = (float*)d_out;           // (4, 4096, 64)

    qkv_gemm_kernel<<<dim3(M_ROWS / 64, 3), 256>>>(x, W, bias);
    attn_kernel<<<dim3(T_SEQ / 64, B_SZ), 256>>>(out);
}

// round 5
// speedup vs baseline: 1.5603x; 1.5603x over previous
#include <cuda_runtime.h>
#include <cuda_bf16.h>

#define T_SEQ 4096
#define B_SZ  4
#define D_IN  1024
#define P_DIM 64
#define M_ROWS (B_SZ * T_SEQ)   // 16384

// qkv scratch: [head (q/k/v)][m = b*T + t][p]
__device__ __align__(16) float g_qkv[3u * M_ROWS * P_DIM];

// ---------------------------------------------------------------------------
// QKV projection: (16384 x 1024) @ (1024 x 192) + bias, scattered into q/k/v
// ---------------------------------------------------------------------------
__global__ __launch_bounds__(256) void qkv_gemm_kernel(
    const float* __restrict__ x,
    const float* __restrict__ W,
    const float* __restrict__ bias)
{
    __shared__ float As[32][68];   // [k][m]
    __shared__ float Bs[32][68];   // [k][n]

    const int m0   = blockIdx.x * 64;
    const int head = blockIdx.y;
    const int n0   = head * 64;
    const int tid  = threadIdx.x;
    const int tx   = tid & 15;
    const int ty   = tid >> 4;

    float acc[4][4];
#pragma unroll
    for (int i = 0; i < 4; i++)
#pragma unroll
        for (int j = 0; j < 4; j++) acc[i][j] = 0.f;

    for (int k0 = 0; k0 < D_IN; k0 += 32) {
#pragma unroll
        for (int i = 0; i < 2; i++) {
            int s   = tid + i * 256;
            int row = s >> 3;
            int kc  = s & 7;
            float4 xv = *(const float4*)&x[(size_t)(m0 + row) * D_IN + k0 + kc * 4];
            As[kc * 4 + 0][row] = xv.x;
            As[kc * 4 + 1][row] = xv.y;
            As[kc * 4 + 2][row] = xv.z;
            As[kc * 4 + 3][row] = xv.w;
        }
#pragma unroll
        for (int i = 0; i < 2; i++) {
            int s  = tid + i * 256;
            int kk = s >> 4;
            int nc = s & 15;
            *(float4*)&Bs[kk][nc * 4] =
                *(const float4*)&W[(size_t)(k0 + kk) * 192 + n0 + nc * 4];
        }
        __syncthreads();

#pragma unroll
        for (int kk = 0; kk < 32; kk++) {
            float4 a4 = *(float4*)&As[kk][ty * 4];
            float4 b4 = *(float4*)&Bs[kk][tx * 4];
            float av[4] = {a4.x, a4.y, a4.z, a4.w};
            float bv[4] = {b4.x, b4.y, b4.z, b4.w};
#pragma unroll
            for (int i = 0; i < 4; i++)
#pragma unroll
                for (int j = 0; j < 4; j++)
                    acc[i][j] += av[i] * bv[j];
        }
        __syncthreads();
    }

    float4 bb = *(const float4*)&bias[n0 + tx * 4];
    float bv[4] = {bb.x, bb.y, bb.z, bb.w};
    float* outp = g_qkv + (size_t)head * M_ROWS * P_DIM;
#pragma unroll
    for (int i = 0; i < 4; i++) {
        int m = m0 + ty * 4 + i;
        float4 o;
        o.x = acc[i][0] + bv[0];
        o.y = acc[i][1] + bv[1];
        o.z = acc[i][2] + bv[2];
        o.w = acc[i][3] + bv[3];
        *(float4*)&outp[(size_t)m * P_DIM + tx * 4] = o;
    }
}

// ---------------------------------------------------------------------------
// Flash-style causal attention, register-blocked.
// Block: 64 query rows x 64-key tiles, 128 threads.
//   thread = (rowg = tid>>4 in 0..7, keyg = tid&15)
//   owns 8 query rows (rowg*8+i), 4 keys (keyg+16*j), 4 out dims (keyg*4..+3)
// Shared stride 68 floats; all LDS/STS patterns conflict-free per 8-lane phase.
// Dynamic smem 68KB: Qs|Ks|Vs|Ps each [64][68].
// ---------------------------------------------------------------------------
__global__ __launch_bounds__(128) void attn_kernel(float* __restrict__ out)
{
    extern __shared__ float sm[];
    float* Qs = sm;                 // [64][68]
    float* Ks = sm + 4352;          // [64][68]
    float* Vs = sm + 8704;          // [64][68]
    float* Ps = sm + 13056;         // [64][68]

    const int b    = blockIdx.y;
    const int qt   = (int)gridDim.x - 1 - (int)blockIdx.x;  // heavy blocks first
    const int tid  = threadIdx.x;
    const int rowg = tid >> 4;      // 0..7
    const int keyg = tid & 15;      // 0..15
    const int r0   = rowg * 8;      // local row base

    const float* qg = g_qkv;
    const float* kg = g_qkv + (size_t)M_ROWS * P_DIM;
    const float* vg = g_qkv + (size_t)2 * M_ROWS * P_DIM;

    const int qrow0 = b * T_SEQ + qt * 64;

    // load Q tile: 64 rows x 16 f4 = 1024 slots, 8 per thread (coalesced, CF)
#pragma unroll
    for (int it = 0; it < 8; it++) {
        int s   = tid + it * 128;
        int row = s >> 4;
        int c   = s & 15;
        *(float4*)&Qs[row * 68 + c * 4] =
            *(const float4*)&qg[(size_t)(qrow0 + row) * P_DIM + c * 4];
    }

    float o[8][4], m[8], l[8];
#pragma unroll
    for (int i = 0; i < 8; i++) {
        m[i] = -1e30f; l[i] = 0.f;
        o[i][0] = o[i][1] = o[i][2] = o[i][3] = 0.f;
    }

    for (int kt = 0; kt <= qt; kt++) {
        __syncthreads();   // prior Vs/Ps consumption done (also covers Qs on iter 0 via next sync)
        const int krow0 = b * T_SEQ + kt * 64;
#pragma unroll
        for (int it = 0; it < 8; it++) {
            int s   = tid + it * 128;
            int row = s >> 4;
            int c   = s & 15;
            *(float4*)&Ks[row * 68 + c * 4] =
                *(const float4*)&kg[(size_t)(krow0 + row) * P_DIM + c * 4];
            *(float4*)&Vs[row * 68 + c * 4] =
                *(const float4*)&vg[(size_t)(krow0 + row) * P_DIM + c * 4];
        }
        __syncthreads();

        // ---- S = Q K^T : sv[8 rows][4 keys] ----
        float sv[8][4];
#pragma unroll
        for (int i = 0; i < 8; i++)
            sv[i][0] = sv[i][1] = sv[i][2] = sv[i][3] = 0.f;

#pragma unroll
        for (int p4 = 0; p4 < 16; p4++) {
            float4 kv[4];
#pragma unroll
            for (int j = 0; j < 4; j++)
                kv[j] = *(float4*)&Ks[(keyg + 16 * j) * 68 + p4 * 4];
#pragma unroll
            for (int i = 0; i < 8; i++) {
                float4 q4 = *(float4*)&Qs[(r0 + i) * 68 + p4 * 4];
#pragma unroll
                for (int j = 0; j < 4; j++) {
                    sv[i][j] += q4.x * kv[j].x;
                    sv[i][j] += q4.y * kv[j].y;
                    sv[i][j] += q4.z * kv[j].z;
                    sv[i][j] += q4.w * kv[j].w;
                }
            }
        }

        // ---- causal mask (diagonal tile only) ----
        if (kt == qt) {
#pragma unroll
            for (int i = 0; i < 8; i++) {
                int rl = r0 + i;   // local row == local key threshold on diagonal
#pragma unroll
                for (int j = 0; j < 4; j++)
                    if (keyg + 16 * j > rl) sv[i][j] = -1e30f;
            }
        }

        // ---- online softmax (per row, reduced across 16 keyg lanes) ----
#pragma unroll
        for (int i = 0; i < 8; i++) {
            float tmax = fmaxf(fmaxf(sv[i][0], sv[i][1]), fmaxf(sv[i][2], sv[i][3]));
            tmax = fmaxf(tmax, __shfl_xor_sync(0xffffffffu, tmax, 1));
            tmax = fmaxf(tmax, __shfl_xor_sync(0xffffffffu, tmax, 2));
            tmax = fmaxf(tmax, __shfl_xor_sync(0xffffffffu, tmax, 4));
            tmax = fmaxf(tmax, __shfl_xor_sync(0xffffffffu, tmax, 8));

            float mnew  = fmaxf(m[i], tmax);
            float scale = __expf(m[i] - mnew);
            float lsum  = 0.f;
#pragma unroll
            for (int j = 0; j < 4; j++) {
                float p = __expf(sv[i][j] - mnew);
                lsum += p;
                Ps[(r0 + i) * 68 + keyg + 16 * j] = p;  // scalar STS, CF (row const per phase)
            }
            lsum += __shfl_xor_sync(0xffffffffu, lsum, 1);
            lsum += __shfl_xor_sync(0xffffffffu, lsum, 2);
            lsum += __shfl_xor_sync(0xffffffffu, lsum, 4);
            lsum += __shfl_xor_sync(0xffffffffu, lsum, 8);

            l[i] = l[i] * scale + lsum;
            m[i] = mnew;
            o[i][0] *= scale; o[i][1] *= scale; o[i][2] *= scale; o[i][3] *= scale;
        }
        __syncthreads();

        // ---- O += P V : o[8 rows][4 dims], dims = keyg*4..+3 ----
#pragma unroll
        for (int j4 = 0; j4 < 16; j4++) {
            float4 v4[4];
#pragma unroll
            for (int j = 0; j < 4; j++)
                v4[j] = *(float4*)&Vs[(j4 * 4 + j) * 68 + keyg * 4];
#pragma unroll
            for (int i = 0; i < 8; i++) {
                float4 p4 = *(float4*)&Ps[(r0 + i) * 68 + j4 * 4];
                o[i][0] += p4.x * v4[0].x; o[i][0] += p4.y * v4[1].x;
                o[i][0] += p4.z * v4[2].x; o[i][0] += p4.w * v4[3].x;
                o[i][1] += p4.x * v4[0].y; o[i][1] += p4.y * v4[1].y;
                o[i][1] += p4.z * v4[2].y; o[i][1] += p4.w * v4[3].y;
                o[i][2] += p4.x * v4[0].z; o[i][2] += p4.y * v4[1].z;
                o[i][2] += p4.z * v4[2].z; o[i][2] += p4.w * v4[3].z;
                o[i][3] += p4.x * v4[0].w; o[i][3] += p4.y * v4[1].w;
                o[i][3] += p4.z * v4[2].w; o[i][3] += p4.w * v4[3].w;
            }
        }
    }

    // ---- epilogue ----
#pragma unroll
    for (int i = 0; i < 8; i++) {
        float inv = 1.0f / l[i];
        float4 ov;
        ov.x = o[i][0] * inv;
        ov.y = o[i][1] * inv;
        ov.z = o[i][2] * inv;
        ov.w = o[i][3] * inv;
        *(float4*)&out[(size_t)(qrow0 + r0 + i) * P_DIM + keyg * 4] = ov;
    }
}

#define ATTN_SMEM (4 * 64 * 68 * 4)   // 69632 bytes

extern "C" void kernel_launch(void* const* d_in, const int* in_sizes, int n_in,
                              void* d_out, int out_size)
{
    const float* x    = (const float*)d_in[0];   // (4, 4096, 1024)
    const float* W    = (const float*)d_in[1];   // (1024, 192)
    const float* bias = (const float*)d_in[2];   // (192,)
    float* out        = (float*)d_out;           // (4, 4096, 64)

    cudaFuncSetAttribute(attn_kernel,
                         cudaFuncAttributeMaxDynamicSharedMemorySize, ATTN_SMEM);

    qkv_gemm_kernel<<<dim3(M_ROWS / 64, 3), 256>>>(x, W, bias);
    attn_kernel<<<dim3(T_SEQ / 64, B_SZ), 128, ATTN_SMEM>>>(out);
}

// round 8
// speedup vs baseline: 2.2088x; 1.4156x over previous
#include <cuda_runtime.h>
#include <cuda_bf16.h>

#define T_SEQ 4096
#define B_SZ  4
#define D_IN  1024
#define P_DIM 64
#define M_ROWS (B_SZ * T_SEQ)   // 16384
#define NSPLIT 2

// qkv scratch: [head (q/k/v)][m = b*T + t][p]
__device__ __align__(16) float g_qkv[3u * M_ROWS * P_DIM];
// split partials: unnormalized O, and (m, l) per row per split
__device__ __align__(16) float g_po[NSPLIT * M_ROWS * P_DIM];
__device__ __align__(16) float g_pml[NSPLIT * M_ROWS * 2];

// ---------------------------------------------------------------------------
// QKV projection: (16384 x 1024) @ (1024 x 192) + bias, scattered into q/k/v
// ---------------------------------------------------------------------------
__global__ __launch_bounds__(256) void qkv_gemm_kernel(
    const float* __restrict__ x,
    const float* __restrict__ W,
    const float* __restrict__ bias)
{
    __shared__ float As[32][68];   // [k][m]
    __shared__ float Bs[32][68];   // [k][n]

    const int m0   = blockIdx.x * 64;
    const int head = blockIdx.y;
    const int n0   = head * 64;
    const int tid  = threadIdx.x;
    const int tx   = tid & 15;
    const int ty   = tid >> 4;

    float acc[4][4];
#pragma unroll
    for (int i = 0; i < 4; i++)
#pragma unroll
        for (int j = 0; j < 4; j++) acc[i][j] = 0.f;

    for (int k0 = 0; k0 < D_IN; k0 += 32) {
#pragma unroll
        for (int i = 0; i < 2; i++) {
            int s   = tid + i * 256;
            int row = s >> 3;
            int kc  = s & 7;
            float4 xv = *(const float4*)&x[(size_t)(m0 + row) * D_IN + k0 + kc * 4];
            As[kc * 4 + 0][row] = xv.x;
            As[kc * 4 + 1][row] = xv.y;
            As[kc * 4 + 2][row] = xv.z;
            As[kc * 4 + 3][row] = xv.w;
        }
#pragma unroll
        for (int i = 0; i < 2; i++) {
            int s  = tid + i * 256;
            int kk = s >> 4;
            int nc = s & 15;
            *(float4*)&Bs[kk][nc * 4] =
                *(const float4*)&W[(size_t)(k0 + kk) * 192 + n0 + nc * 4];
        }
        __syncthreads();

#pragma unroll
        for (int kk = 0; kk < 32; kk++) {
            float4 a4 = *(float4*)&As[kk][ty * 4];
            float4 b4 = *(float4*)&Bs[kk][tx * 4];
            float av[4] = {a4.x, a4.y, a4.z, a4.w};
            float bv[4] = {b4.x, b4.y, b4.z, b4.w};
#pragma unroll
            for (int i = 0; i < 4; i++)
#pragma unroll
                for (int j = 0; j < 4; j++)
                    acc[i][j] += av[i] * bv[j];
        }
        __syncthreads();
    }

    float4 bb = *(const float4*)&bias[n0 + tx * 4];
    float bv[4] = {bb.x, bb.y, bb.z, bb.w};
    float* outp = g_qkv + (size_t)head * M_ROWS * P_DIM;
#pragma unroll
    for (int i = 0; i < 4; i++) {
        int m = m0 + ty * 4 + i;
        float4 o;
        o.x = acc[i][0] + bv[0];
        o.y = acc[i][1] + bv[1];
        o.z = acc[i][2] + bv[2];
        o.w = acc[i][3] + bv[3];
        *(float4*)&outp[(size_t)m * P_DIM + tx * 4] = o;
    }
}

// ---------------------------------------------------------------------------
// Flash-style causal attention, register-blocked + key-split.
// Block = (query tile qt of 64 rows, batch b, split s of NSPLIT).
// Split s handles key tiles kt in [s*n/NSPLIT, (s+1)*n/NSPLIT), n = qt+1.
// 128 threads: rowg = tid>>4 (8 rows each), keyg = tid&15 (4 keys, 4 out dims).
// Writes unnormalized O plus (m, l) partials to global scratch.
// ---------------------------------------------------------------------------
__global__ __launch_bounds__(128) void attn_kernel()
{
    extern __shared__ float sm[];
    float* Qs = sm;                 // [64][68]
    float* Ks = sm + 4352;          // [64][68]
    float* Vs = sm + 8704;          // [64][68]
    float* Ps = sm + 13056;         // [64][68]

    const int b    = blockIdx.y;
    const int qt   = (int)gridDim.x - 1 - (int)blockIdx.x;  // heavy blocks first
    const int sp   = blockIdx.z;
    const int tid  = threadIdx.x;
    const int rowg = tid >> 4;      // 0..7
    const int keyg = tid & 15;      // 0..15
    const int r0   = rowg * 8;

    const int n   = qt + 1;
    const int kt0 = sp * n / NSPLIT;
    const int kt1 = (sp + 1) * n / NSPLIT;

    const float* qg = g_qkv;
    const float* kg = g_qkv + (size_t)M_ROWS * P_DIM;
    const float* vg = g_qkv + (size_t)2 * M_ROWS * P_DIM;

    const int qrow0 = b * T_SEQ + qt * 64;

    // load Q tile: 64 rows x 16 f4 = 1024 slots, 8 per thread (coalesced, CF)
#pragma unroll
    for (int it = 0; it < 8; it++) {
        int s   = tid + it * 128;
        int row = s >> 4;
        int c   = s & 15;
        *(float4*)&Qs[row * 68 + c * 4] =
            *(const float4*)&qg[(size_t)(qrow0 + row) * P_DIM + c * 4];
    }

    float o[8][4], m[8], l[8];
#pragma unroll
    for (int i = 0; i < 8; i++) {
        m[i] = -1e30f; l[i] = 0.f;
        o[i][0] = o[i][1] = o[i][2] = o[i][3] = 0.f;
    }

    for (int kt = kt0; kt < kt1; kt++) {
        __syncthreads();
        const int krow0 = b * T_SEQ + kt * 64;
#pragma unroll
        for (int it = 0; it < 8; it++) {
            int s   = tid + it * 128;
            int row = s >> 4;
            int c   = s & 15;
            *(float4*)&Ks[row * 68 + c * 4] =
                *(const float4*)&kg[(size_t)(krow0 + row) * P_DIM + c * 4];
            *(float4*)&Vs[row * 68 + c * 4] =
                *(const float4*)&vg[(size_t)(krow0 + row) * P_DIM + c * 4];
        }
        __syncthreads();

        // ---- S = Q K^T : sv[8 rows][4 keys] ----
        float sv[8][4];
#pragma unroll
        for (int i = 0; i < 8; i++)
            sv[i][0] = sv[i][1] = sv[i][2] = sv[i][3] = 0.f;

#pragma unroll
        for (int p4 = 0; p4 < 16; p4++) {
            float4 kv[4];
#pragma unroll
            for (int j = 0; j < 4; j++)
                kv[j] = *(float4*)&Ks[(keyg + 16 * j) * 68 + p4 * 4];
#pragma unroll
            for (int i = 0; i < 8; i++) {
                float4 q4 = *(float4*)&Qs[(r0 + i) * 68 + p4 * 4];
#pragma unroll
                for (int j = 0; j < 4; j++) {
                    sv[i][j] += q4.x * kv[j].x;
                    sv[i][j] += q4.y * kv[j].y;
                    sv[i][j] += q4.z * kv[j].z;
                    sv[i][j] += q4.w * kv[j].w;
                }
            }
        }

        // ---- causal mask (diagonal tile only) ----
        if (kt == qt) {
#pragma unroll
            for (int i = 0; i < 8; i++) {
                int rl = r0 + i;
#pragma unroll
                for (int j = 0; j < 4; j++)
                    if (keyg + 16 * j > rl) sv[i][j] = -1e30f;
            }
        }

        // ---- online softmax (per row, reduced across 16 keyg lanes) ----
#pragma unroll
        for (int i = 0; i < 8; i++) {
            float tmax = fmaxf(fmaxf(sv[i][0], sv[i][1]), fmaxf(sv[i][2], sv[i][3]));
            tmax = fmaxf(tmax, __shfl_xor_sync(0xffffffffu, tmax, 1));
            tmax = fmaxf(tmax, __shfl_xor_sync(0xffffffffu, tmax, 2));
            tmax = fmaxf(tmax, __shfl_xor_sync(0xffffffffu, tmax, 4));
            tmax = fmaxf(tmax, __shfl_xor_sync(0xffffffffu, tmax, 8));

            float mnew  = fmaxf(m[i], tmax);
            float scale = __expf(m[i] - mnew);
            float lsum  = 0.f;
#pragma unroll
            for (int j = 0; j < 4; j++) {
                float p = __expf(sv[i][j] - mnew);
                lsum += p;
                Ps[(r0 + i) * 68 + keyg + 16 * j] = p;
            }
            lsum += __shfl_xor_sync(0xffffffffu, lsum, 1);
            lsum += __shfl_xor_sync(0xffffffffu, lsum, 2);
            lsum += __shfl_xor_sync(0xffffffffu, lsum, 4);
            lsum += __shfl_xor_sync(0xffffffffu, lsum, 8);

            l[i] = l[i] * scale + lsum;
            m[i] = mnew;
            o[i][0] *= scale; o[i][1] *= scale; o[i][2] *= scale; o[i][3] *= scale;
        }
        __syncthreads();

        // ---- O += P V ----
#pragma unroll
        for (int j4 = 0; j4 < 16; j4++) {
            float4 v4[4];
#pragma unroll
            for (int j = 0; j < 4; j++)
                v4[j] = *(float4*)&Vs[(j4 * 4 + j) * 68 + keyg * 4];
#pragma unroll
            for (int i = 0; i < 8; i++) {
                float4 p4 = *(float4*)&Ps[(r0 + i) * 68 + j4 * 4];
                o[i][0] += p4.x * v4[0].x; o[i][0] += p4.y * v4[1].x;
                o[i][0] += p4.z * v4[2].x; o[i][0] += p4.w * v4[3].x;
                o[i][1] += p4.x * v4[0].y; o[i][1] += p4.y * v4[1].y;
                o[i][1] += p4.z * v4[2].y; o[i][1] += p4.w * v4[3].y;
                o[i][2] += p4.x * v4[0].z; o[i][2] += p4.y * v4[1].z;
                o[i][2] += p4.z * v4[2].z; o[i][2] += p4.w * v4[3].z;
                o[i][3] += p4.x * v4[0].w; o[i][3] += p4.y * v4[1].w;
                o[i][3] += p4.z * v4[2].w; o[i][3] += p4.w * v4[3].w;
            }
        }
    }

    // ---- write split partials (unnormalized O, and m,l) ----
    float* po  = g_po  + (size_t)sp * M_ROWS * P_DIM;
    float* pml = g_pml + (size_t)sp * M_ROWS * 2;
#pragma unroll
    for (int i = 0; i < 8; i++) {
        int row = qrow0 + r0 + i;
        float4 ov;
        ov.x = o[i][0]; ov.y = o[i][1]; ov.z = o[i][2]; ov.w = o[i][3];
        *(float4*)&po[(size_t)row * P_DIM + keyg * 4] = ov;
        if (keyg == 0) {
            pml[row * 2 + 0] = m[i];
            pml[row * 2 + 1] = l[i];
        }
    }
}

// ---------------------------------------------------------------------------
// Combine the NSPLIT partials: O = sum_s(o_s * e^{m_s-M}) / sum_s(l_s * e^{m_s-M})
// One thread per (row, f4-chunk): 16384*16 threads.
// ---------------------------------------------------------------------------
__global__ __launch_bounds__(256) void combine_kernel(float* __restrict__ out)
{
    int idx = blockIdx.x * 256 + threadIdx.x;
    int row = idx >> 4;
    int c   = idx & 15;

    float m0 = g_pml[row * 2 + 0];
    float l0 = g_pml[row * 2 + 1];
    float m1 = g_pml[(size_t)M_ROWS * 2 + row * 2 + 0];
    float l1 = g_pml[(size_t)M_ROWS * 2 + row * 2 + 1];

    float M  = fmaxf(m0, m1);
    float w0 = __expf(m0 - M);
    float w1 = __expf(m1 - M);
    float inv = 1.0f / (l0 * w0 + l1 * w1);

    float4 a = *(const float4*)&g_po[(size_t)row * P_DIM + c * 4];
    float4 b = *(const float4*)&g_po[(size_t)(M_ROWS + row) * P_DIM + c * 4];
    float4 r;
    r.x = (a.x * w0 + b.x * w1) * inv;
    r.y = (a.y * w0 + b.y * w1) * inv;
    r.z = (a.z * w0 + b.z * w1) * inv;
    r.w = (a.w * w0 + b.w * w1) * inv;
    *(float4*)&out[(size_t)row * P_DIM + c * 4] = r;
}

#define ATTN_SMEM (4 * 64 * 68 * 4)   // 69632 bytes

extern "C" void kernel_launch(void* const* d_in, const int* in_sizes, int n_in,
                              void* d_out, int out_size)
{
    const float* x    = (const float*)d_in[0];   // (4, 4096, 1024)
    const float* W    = (const float*)d_in[1];   // (1024, 192)
    const float* bias = (const float*)d_in[2];   // (192,)
    float* out        = (float*)d_out;           // (4, 4096, 64)

    cudaFuncSetAttribute(attn_kernel,
                         cudaFuncAttributeMaxDynamicSharedMemorySize, ATTN_SMEM);

    qkv_gemm_kernel<<<dim3(M_ROWS / 64, 3), 256>>>(x, W, bias);
    attn_kernel<<<dim3(T_SEQ / 64, B_SZ, NSPLIT), 128, ATTN_SMEM>>>();
    combine_kernel<<<(M_ROWS * 16) / 256, 256>>>(out);
}